// round 12
// baseline (speedup 1.0000x reference)
#include <cuda_runtime.h>
#include <cuda_fp16.h>
#include <math.h>

#define BB 2
#define QQ 2048
#define KSEQ 2048
#define DMODEL 512
#define NH 8
#define NF 5
#define DH 64

// Scratch (no cudaMalloc allowed)
__device__ float g_q[BB * QQ * DMODEL];
__device__ float g_v[BB * KSEQ * DMODEL];
__device__ float g_ctx[BB * QQ * DMODEL];
__device__ unsigned g_kh[BB * NH * KSEQ * 32];          // K fp16 packed dh-pairs
__device__ unsigned g_vh[BB * NH * DH * (KSEQ / 2)];    // V fp16 packed key-pairs
__device__ unsigned g_wb[4 * DMODEL * (DMODEL / 2)];    // W big fp16, [n][kpair]
__device__ unsigned g_ws[4 * DMODEL * (DMODEL / 2)];    // W small fp16

__device__ __forceinline__ float ex2f(float x) { float r; asm("ex2.approx.f32 %0, %1;" : "=f"(r) : "f"(x)); return r; }
__device__ __forceinline__ float sqrt_ap(float x) { float r; asm("sqrt.approx.f32 %0, %1;" : "=f"(r) : "f"(x)); return r; }
__device__ __forceinline__ unsigned packh2(float x, float y) {
    __half2 h = __floats2half2_rn(x, y);
    return *reinterpret_cast<unsigned*>(&h);
}
__device__ __forceinline__ unsigned smaddr(const void* p) {
    unsigned r;
    asm("{ .reg .u64 t; cvta.to.shared.u64 t, %1; cvt.u32.u64 %0, t; }" : "=r"(r) : "l"(p));
    return r;
}
__device__ __forceinline__ void ldsm4(unsigned& r0, unsigned& r1, unsigned& r2, unsigned& r3, unsigned a) {
    asm volatile("ldmatrix.sync.aligned.m8n8.x4.shared.b16 {%0,%1,%2,%3}, [%4];"
                 : "=r"(r0), "=r"(r1), "=r"(r2), "=r"(r3) : "r"(a));
}

#define CP16(dst, src) asm volatile("cp.async.cg.shared.global [%0], [%1], 16;" :: "r"(dst), "l"(src))
#define CP_COMMIT()    asm volatile("cp.async.commit_group;")
#define CP_WAIT0()     asm volatile("cp.async.wait_group 0;" ::: "memory")
#define CP_WAIT1()     asm volatile("cp.async.wait_group 1;" ::: "memory")

#define MMA_F16(C, A0, A1, A2, A3, B0, B1)                                  \
    asm volatile("mma.sync.aligned.m16n8k16.row.col.f32.f16.f16.f32 "       \
        "{%0,%1,%2,%3}, {%4,%5,%6,%7}, {%8,%9}, {%0,%1,%2,%3};"             \
        : "+f"((C)[0]), "+f"((C)[1]), "+f"((C)[2]), "+f"((C)[3])            \
        : "r"(A0), "r"(A1), "r"(A2), "r"(A3), "r"(B0), "r"(B1))

// ---------------------------------------------------------------------------
// Pack W: split into fp16 big + fp16 small, transposed to [n][kpair] packed.
// ---------------------------------------------------------------------------
struct PackWBatch { const float* in[4]; };

__global__ void pack_w_kernel(PackWBatch args)
{
    __shared__ float t[32][33];
    const float* in = args.in[blockIdx.z];
    unsigned zoff = blockIdx.z * DMODEL * (DMODEL / 2);
    int k0 = blockIdx.y * 32, n0 = blockIdx.x * 32;
    int tx = threadIdx.x, ty = threadIdx.y;
    #pragma unroll
    for (int j = 0; j < 4; j++)
        t[ty + j * 8][tx] = in[(size_t)(k0 + ty + j * 8) * DMODEL + n0 + tx];
    __syncthreads();
    int idx = ty * 32 + tx;
    int kp = idx & 15, nl = idx >> 4;
    #pragma unroll
    for (int j2 = 0; j2 < 2; j2++) {
        int n = nl + j2 * 16;
        float w0 = t[2 * kp][n], w1 = t[2 * kp + 1][n];
        __half2 hb = __floats2half2_rn(w0, w1);
        float s0 = w0 - __low2float(hb);
        float s1 = w1 - __high2float(hb);
        unsigned ub = *reinterpret_cast<unsigned*>(&hb);
        size_t o = zoff + (size_t)(n0 + n) * 256 + (k0 >> 1) + kp;
        g_wb[o] = ub;
        g_ws[o] = packh2(s0, s1);
    }
}

// ---------------------------------------------------------------------------
// Pack V: fp32 [b][key][DM] -> fp16 key-pair packed [b][h][dh][kp]
// ---------------------------------------------------------------------------
__global__ __launch_bounds__(256) void pack_v_kernel()
{
    __shared__ unsigned sv[64 * 64];
    int bh = blockIdx.y;
    int b = bh >> 3, h = bh & 7;
    int k0 = blockIdx.x * 64;
    int tid = threadIdx.x;
    int dh = tid & 63, kq = tid >> 6;
    const float* vb = g_v + (size_t)(b * KSEQ + k0) * DMODEL + h * DH + dh;
    #pragma unroll
    for (int j = 0; j < 8; j++) {
        int kp = kq * 8 + j;
        float r0 = vb[(size_t)(2 * kp) * DMODEL];
        float r1 = vb[(size_t)(2 * kp + 1) * DMODEL];
        sv[kp * 64 + dh] = packh2(r0, r1);
    }
    __syncthreads();
    int row = tid >> 2, cs = (tid & 3) * 8;
    unsigned* ob = g_vh + ((size_t)(b * NH + h) * DH + row) * (KSEQ / 2) + (k0 >> 1) + cs;
    #pragma unroll
    for (int q = 0; q < 2; q++) {
        uint4 v;
        v.x = sv[(cs + q * 4 + 0) * 64 + row];
        v.y = sv[(cs + q * 4 + 1) * 64 + row];
        v.z = sv[(cs + q * 4 + 2) * 64 + row];
        v.w = sv[(cs + q * 4 + 3) * 64 + row];
        *(uint4*)(ob + q * 4) = v;
    }
}

// ---------------------------------------------------------------------------
// fp16 2-mma GEMM: C = (A @ W^T + bias)*scale, W pre-split (big+small fp16).
// CTA tile 128x64 (acc regs halved -> 2 CTAs/SM), BK=32, 8 warps (32x32).
// Pipeline: wait -> sync -> issue-next-W -> mma -> store-next-A.
// ---------------------------------------------------------------------------
struct GemmBatch {
    const float* A[3]; const unsigned* Wb[3]; const unsigned* Ws[3];
    const float* bias[3]; float* C[3]; float scale[3]; int omode[3];
};

#define GS 20
#define SSTR 5120                       // u32/stage: A 128*20 + Wb 64*20 + Ws 64*20
#define GEMM_SMEM (2 * SSTR * 4)        // 40960 B

__global__ __launch_bounds__(256, 2) void gemm_f16_kernel(GemmBatch args)
{
    extern __shared__ unsigned su[];

    int z = blockIdx.z;
    const float* A = args.A[z];
    const float* bias = args.bias[z];
    float* C = args.C[z];
    float scale = args.scale[z];
    int omode = args.omode[z];

    int tid = threadIdx.x, w = tid >> 5, lane = tid & 31;
    int g = lane >> 2, tig = lane & 3;
    int row0 = blockIdx.y * 128, col0 = blockIdx.x * 64;
    int wm = (w & 3) * 32, wn = (w >> 2) * 32;

    float acc[2][4][4];
    #pragma unroll
    for (int mf = 0; mf < 2; mf++)
        #pragma unroll
        for (int nf = 0; nf < 4; nf++)
            acc[mf][nf][0] = acc[mf][nf][1] = acc[mf][nf][2] = acc[mf][nf][3] = 0.f;

    int r = tid >> 1, c0 = (tid & 1) << 3;     // A: row, u32 col base
    int wr = tid >> 2, wc = (tid & 3) << 2;    // W: row, u32 col base
    const float* Ap = A + (size_t)(row0 + r) * DMODEL + (c0 << 1);
    const unsigned* Wbp = args.Wb[z] + (size_t)(col0 + wr) * 256 + wc;
    const unsigned* Wsp = args.Ws[z] + (size_t)(col0 + wr) * 256 + wc;
    unsigned sb = smaddr(su);

    float4 av[4];
    #pragma unroll
    for (int j = 0; j < 4; j++) av[j] = *(const float4*)(Ap + j * 4);

    #define STS_A(st)                                                        \
    do {                                                                     \
        unsigned* Ah_ = su + (st) * SSTR;                                    \
        uint4 p0, p1;                                                        \
        p0.x = packh2(av[0].x, av[0].y); p0.y = packh2(av[0].z, av[0].w);    \
        p0.z = packh2(av[1].x, av[1].y); p0.w = packh2(av[1].z, av[1].w);    \
        p1.x = packh2(av[2].x, av[2].y); p1.y = packh2(av[2].z, av[2].w);    \
        p1.z = packh2(av[3].x, av[3].y); p1.w = packh2(av[3].z, av[3].w);    \
        *(uint4*)&Ah_[r * GS + c0] = p0;                                     \
        *(uint4*)&Ah_[r * GS + c0 + 4] = p1;                                 \
    } while (0)

    #define ISSUE_W(it, st)                                                  \
    do {                                                                     \
        unsigned wbd = sb + ((st) * SSTR + 2560 + wr * GS + wc) * 4;         \
        unsigned wsd = wbd + 1280 * 4;                                       \
        CP16(wbd, Wbp + (it) * 16);                                          \
        CP16(wsd, Wsp + (it) * 16);                                          \
        CP_COMMIT();                                                         \
    } while (0)

    STS_A(0);
    ISSUE_W(0, 0);

    const int NT = DMODEL / 32;   // 16
    for (int it = 0; it < NT; it++) {
        int cur = it & 1;
        bool nx = (it + 1) < NT;
        if (nx) {
            #pragma unroll
            for (int j = 0; j < 4; j++)
                av[j] = *(const float4*)(Ap + (it + 1) * 32 + j * 4);
        }
        CP_WAIT0();
        __syncthreads();
        if (nx) ISSUE_W(it + 1, cur ^ 1);

        unsigned* Ah = su + cur * SSTR;
        unsigned* Wbm = Ah + 2560;
        unsigned* Wsm = Ah + 3840;

        #pragma unroll
        for (int s = 0; s < 2; s++) {
            unsigned af[2][4];
            #pragma unroll
            for (int mf = 0; mf < 2; mf++) {
                int rb = (wm + mf * 16 + g) * GS;
                int cb = s * 8 + tig;
                af[mf][0] = Ah[rb + cb];
                af[mf][1] = Ah[rb + 8 * GS + cb];
                af[mf][2] = Ah[rb + cb + 4];
                af[mf][3] = Ah[rb + 8 * GS + cb + 4];
            }
            #pragma unroll
            for (int nf = 0; nf < 4; nf++) {
                int br = (wn + nf * 8 + g) * GS + s * 8 + tig;
                unsigned bb0 = Wbm[br], bb1 = Wbm[br + 4];
                unsigned bs0 = Wsm[br], bs1 = Wsm[br + 4];
                #pragma unroll
                for (int mf = 0; mf < 2; mf++) {
                    MMA_F16(acc[mf][nf], af[mf][0], af[mf][1], af[mf][2], af[mf][3], bs0, bs1);
                    MMA_F16(acc[mf][nf], af[mf][0], af[mf][1], af[mf][2], af[mf][3], bb0, bb1);
                }
            }
        }
        if (nx) STS_A(cur ^ 1);
    }
    #undef STS_A
    #undef ISSUE_W

    if (omode == 0) {
        #pragma unroll
        for (int mf = 0; mf < 2; mf++) {
            int rr = row0 + wm + mf * 16 + g;
            #pragma unroll
            for (int nf = 0; nf < 4; nf++) {
                int n = col0 + wn + nf * 8 + 2 * tig;
                float2 bv = *(const float2*)&bias[n];
                *(float2*)&C[(size_t)rr * DMODEL + n] =
                    make_float2((acc[mf][nf][0] + bv.x) * scale, (acc[mf][nf][1] + bv.y) * scale);
                *(float2*)&C[(size_t)(rr + 8) * DMODEL + n] =
                    make_float2((acc[mf][nf][2] + bv.x) * scale, (acc[mf][nf][3] + bv.y) * scale);
            }
        }
    } else {
        #pragma unroll
        for (int mf = 0; mf < 2; mf++) {
            int rr = row0 + wm + mf * 16 + g;
            #pragma unroll
            for (int nf = 0; nf < 4; nf++) {
                int n = col0 + wn + nf * 8 + 2 * tig;
                float2 bv = *(const float2*)&bias[n];
                int h = n >> 6, dhp = (n & 63) >> 1;
                int b0 = rr >> 11, key0 = rr & 2047;
                g_kh[((size_t)(b0 * NH + h) * KSEQ + key0) * 32 + dhp] =
                    packh2(acc[mf][nf][0] + bv.x, acc[mf][nf][1] + bv.y);
                int rr1 = rr + 8;
                int b1 = rr1 >> 11, key1 = rr1 & 2047;
                g_kh[((size_t)(b1 * NH + h) * KSEQ + key1) * 32 + dhp] =
                    packh2(acc[mf][nf][2] + bv.x, acc[mf][nf][3] + bv.y);
            }
        }
    }
}

// ---------------------------------------------------------------------------
// fp16 flash attention. Bias folded into mma accumulator init (computed from
// the LUT BEFORE QK^T); Q pre-scaled by log2e/8 and LUT pre-folded with
// (x*L2E + MB) so post-mma epilogue is just min+ex2 per element.
// K/V fragments loaded via ldmatrix.x4. 3-stage cp.async ring.
// ---------------------------------------------------------------------------
#define TBL 2048
#define SSZ 4736   // u32/stage: K 64*36 + V 64*36 + Kloc 128
#define NSTG 3
#define ATTN_SMEM ((NSTG * SSZ + 2 * TBL) * 4)

__global__ __launch_bounds__(256, 2) void attn_kernel(
    const float* __restrict__ qlocs_g, const float* __restrict__ klocs_g,
    const float* __restrict__ a_g, const float* __restrict__ b_g,
    const float* __restrict__ c_g, const int* __restrict__ valid_lens)
{
    extern __shared__ unsigned smu[];
    float* Tbl = (float*)(smu + NSTG * SSZ);

    const float L2E = 1.4426950408889634f;
    const float MB = -13.0831206542234f;        // -(16*log2e - 10)
    const float IDXS = 2047.0f / 14.2f;
    const float INVS = 14.2f / 2047.0f;

    int bh = blockIdx.y;
    int b = bh >> 3, h = bh & 7;
    int q0 = blockIdx.x * 128;
    int tid = threadIdx.x, w = tid >> 5, lane = tid & 31;
    int g = lane >> 2, tig = lane & 3;
    int vlen = valid_lens[b];

    // ---- RBF bias LUT: entry = (bias(x)*L2E + MB, dbias*L2E) ----
    {
        float af[NF], al[NF], be[NF], ga[NF];
        #pragma unroll
        for (int f = 0; f < NF; f++) {
            float aa = a_g[h * NF + f];
            float bb = fabsf(b_g[h * NF + f]);
            float cc = c_g[h * NF + f];
            af[f] = aa;
            al[f] = -bb * L2E;
            be[f] = 2.0f * bb * cc * L2E;
            ga[f] = -bb * cc * cc * L2E;
        }
        for (int i = tid; i < TBL; i += 256) {
            float x0 = i * INVS, x1 = (i + 1) * INVS;
            float v0 = 0.f, v1 = 0.f;
            #pragma unroll
            for (int f = 0; f < NF; f++) {
                v0 = fmaf(af[f], ex2f(fmaf(fmaf(al[f], x0, be[f]), x0, ga[f])), v0);
                v1 = fmaf(af[f], ex2f(fmaf(fmaf(al[f], x1, be[f]), x1, ga[f])), v1);
            }
            *(float2*)&Tbl[2 * i] = make_float2(fmaf(v0, L2E, MB), (v1 - v0) * L2E);
        }
    }

    // ---- query rows, locations, hoisted Q fragments (Q already *L2E/8) ----
    int qr0 = q0 + w * 16 + g, qr1 = qr0 + 8;
    float2 ql0 = *(const float2*)(qlocs_g + ((size_t)b * QQ + qr0) * 2);
    float2 ql1 = *(const float2*)(qlocs_g + ((size_t)b * QQ + qr1) * 2);

    unsigned qf[4][4];
    {
        const float* qp0 = g_q + ((size_t)(b * QQ + qr0)) * DMODEL + h * DH;
        const float* qp1 = g_q + ((size_t)(b * QQ + qr1)) * DMODEL + h * DH;
        #pragma unroll
        for (int kt = 0; kt < 4; kt++) {
            int base = kt * 16 + 2 * tig;
            float2 x0 = *(const float2*)(qp0 + base);
            float2 x1 = *(const float2*)(qp1 + base);
            float2 x2 = *(const float2*)(qp0 + base + 8);
            float2 x3 = *(const float2*)(qp1 + base + 8);
            qf[kt][0] = packh2(x0.x, x0.y);
            qf[kt][1] = packh2(x1.x, x1.y);
            qf[kt][2] = packh2(x2.x, x2.y);
            qf[kt][3] = packh2(x3.x, x3.y);
        }
    }

    float o[8][4];
    #pragma unroll
    for (int nt = 0; nt < 8; nt++)
        o[nt][0] = o[nt][1] = o[nt][2] = o[nt][3] = 0.f;
    float rs0 = 0.f, rs1 = 0.f;

    unsigned sb = smaddr(smu);
    const unsigned* khb = g_kh + (size_t)(b * NH + h) * KSEQ * 32;
    const unsigned* vhb = g_vh + (size_t)(b * NH + h) * DH * (KSEQ / 2);
    const float* klocs_b = klocs_g + (size_t)b * KSEQ * 2;

    // ldmatrix per-lane offset: tile t = lane>>3 -> (nt pair half, b half)
    unsigned kofs = ((unsigned)((lane >> 4) * 8 + (lane & 7))) * 144u
                  + ((unsigned)((lane >> 3) & 1)) * 16u;

    int ntiles = (vlen + 63) >> 6;

    #define ISSUE_TILE(t, st)                                                \
    do {                                                                     \
        int k0_ = (t) << 6;                                                  \
        unsigned kd = sb + (st) * SSZ * 4;                                   \
        unsigned vd = kd + 2304 * 4;                                         \
        _Pragma("unroll")                                                    \
        for (int i = 0; i < 2; i++) {                                        \
            int idx = tid + i * 256;                                         \
            int row = idx >> 3, ch = (idx & 7) << 2;                         \
            CP16(kd + (row * 36 + ch) * 4, khb + (size_t)(k0_ + row) * 32 + ch); \
            CP16(vd + (row * 36 + ch) * 4, vhb + (size_t)row * (KSEQ / 2) + (k0_ >> 1) + ch); \
        }                                                                    \
        if (tid < 32)                                                        \
            CP16(kd + (4608 + tid * 4) * 4, klocs_b + k0_ * 2 + tid * 4);    \
        CP_COMMIT();                                                         \
    } while (0)

    ISSUE_TILE(0, 0);
    if (ntiles > 1) ISSUE_TILE(1, 1);
    __syncthreads();   // Tbl ready

    int st = 0, ist = 2;
    for (int t = 0; t < ntiles; t++) {
        int k0 = t << 6;
        if (t + 1 < ntiles) CP_WAIT1(); else CP_WAIT0();
        __syncthreads();
        if (t + 2 < ntiles) {
            ISSUE_TILE(t + 2, ist);
            ist = (ist == NSTG - 1) ? 0 : ist + 1;
        }

        unsigned kSm = sb + st * SSZ * 4;
        unsigned vSm = kSm + 2304 * 4;
        const float* Kloc = (const float*)(smu + st * SSZ + 4608);

        // ---- bias -> Sv (accumulator init), BEFORE the mma ----
        float Sv[8][4];
        #pragma unroll
        for (int nt = 0; nt < 8; nt++) {
            int kc0 = nt * 8 + 2 * tig;
            float2 kl0 = *(const float2*)&Kloc[kc0 * 2];
            float2 kl1 = *(const float2*)&Kloc[kc0 * 2 + 2];

            float dx, dy;
            dx = ql0.x - kl0.x; dy = ql0.y - kl0.y; float d0 = sqrt_ap(dx * dx + dy * dy);
            dx = ql0.x - kl1.x; dy = ql0.y - kl1.y; float d1 = sqrt_ap(dx * dx + dy * dy);
            dx = ql1.x - kl0.x; dy = ql1.y - kl0.y; float d2 = sqrt_ap(dx * dx + dy * dy);
            dx = ql1.x - kl1.x; dy = ql1.y - kl1.y; float d3 = sqrt_ap(dx * dx + dy * dy);

            float if0 = d0 * IDXS; int i0 = (int)if0; float fr0 = if0 - (float)i0;
            float if1 = d1 * IDXS; int i1 = (int)if1; float fr1 = if1 - (float)i1;
            float if2 = d2 * IDXS; int i2 = (int)if2; float fr2 = if2 - (float)i2;
            float if3 = d3 * IDXS; int i3 = (int)if3; float fr3 = if3 - (float)i3;
            float2 t0 = *(const float2*)&Tbl[i0 * 2];
            float2 t1 = *(const float2*)&Tbl[i1 * 2];
            float2 t2 = *(const float2*)&Tbl[i2 * 2];
            float2 t3 = *(const float2*)&Tbl[i3 * 2];

            Sv[nt][0] = fmaf(fr0, t0.y, t0.x);
            Sv[nt][1] = fmaf(fr1, t1.y, t1.x);
            Sv[nt][2] = fmaf(fr2, t2.y, t2.x);
            Sv[nt][3] = fmaf(fr3, t3.y, t3.x);
        }

        // ---- Sv += Q K^T (log2e units) via ldmatrix + mma ----
        #pragma unroll
        for (int kt = 0; kt < 4; kt++) {
            #pragma unroll
            for (int i = 0; i < 4; i++) {
                unsigned m0, m1, m2, m3;
                ldsm4(m0, m1, m2, m3, kSm + i * 2304 + kt * 32 + kofs);
                MMA_F16(Sv[2 * i],     qf[kt][0], qf[kt][1], qf[kt][2], qf[kt][3], m0, m1);
                MMA_F16(Sv[2 * i + 1], qf[kt][0], qf[kt][1], qf[kt][2], qf[kt][3], m2, m3);
            }
        }

        // ---- p = ex2(min(Sv, 15)); mask; accumulate row sums ----
        bool full = (k0 + 64) <= vlen;
        #pragma unroll
        for (int nt = 0; nt < 8; nt++) {
            float p0 = ex2f(fminf(Sv[nt][0], 15.0f));
            float p1 = ex2f(fminf(Sv[nt][1], 15.0f));
            float p2 = ex2f(fminf(Sv[nt][2], 15.0f));
            float p3 = ex2f(fminf(Sv[nt][3], 15.0f));
            if (!full) {
                int kc0 = nt * 8 + 2 * tig;
                if (k0 + kc0     >= vlen) { p0 = 0.f; p2 = 0.f; }
                if (k0 + kc0 + 1 >= vlen) { p1 = 0.f; p3 = 0.f; }
            }
            rs0 += p0 + p1;
            rs1 += p2 + p3;
            Sv[nt][0] = p0; Sv[nt][1] = p1; Sv[nt][2] = p2; Sv[nt][3] = p3;
        }

        // ---- O += P V (C-frag pairs pack directly as A-frags) ----
        #pragma unroll
        for (int j = 0; j < 4; j++) {
            unsigned a0 = packh2(Sv[2 * j][0], Sv[2 * j][1]);
            unsigned a1 = packh2(Sv[2 * j][2], Sv[2 * j][3]);
            unsigned a2 = packh2(Sv[2 * j + 1][0], Sv[2 * j + 1][1]);
            unsigned a3 = packh2(Sv[2 * j + 1][2], Sv[2 * j + 1][3]);
            #pragma unroll
            for (int i = 0; i < 4; i++) {
                unsigned m0, m1, m2, m3;
                ldsm4(m0, m1, m2, m3, vSm + i * 2304 + j * 32 + kofs);
                MMA_F16(o[2 * i],     a0, a1, a2, a3, m0, m1);
                MMA_F16(o[2 * i + 1], a0, a1, a2, a3, m2, m3);
            }
        }
        st = (st == NSTG - 1) ? 0 : st + 1;
    }
    #undef ISSUE_TILE

    // ---- normalize + write ----
    rs0 += __shfl_xor_sync(0xffffffffu, rs0, 1);
    rs0 += __shfl_xor_sync(0xffffffffu, rs0, 2);
    rs1 += __shfl_xor_sync(0xffffffffu, rs1, 1);
    rs1 += __shfl_xor_sync(0xffffffffu, rs1, 2);
    float inv0 = 1.0f / rs0, inv1 = 1.0f / rs1;

    float* ob0 = g_ctx + ((size_t)b * QQ + qr0) * DMODEL + h * DH;
    float* ob1 = g_ctx + ((size_t)b * QQ + qr1) * DMODEL + h * DH;
    #pragma unroll
    for (int nt = 0; nt < 8; nt++) {
        *(float2*)(ob0 + nt * 8 + 2 * tig) = make_float2(o[nt][0] * inv0, o[nt][1] * inv0);
        *(float2*)(ob1 + nt * 8 + 2 * tig) = make_float2(o[nt][2] * inv1, o[nt][3] * inv1);
    }
}

// ---------------------------------------------------------------------------
extern "C" void kernel_launch(void* const* d_in, const int* in_sizes, int n_in,
                              void* d_out, int out_size)
{
    const float* qs      = (const float*)d_in[0];
    const float* ks      = (const float*)d_in[1];
    const float* vs      = (const float*)d_in[2];
    const float* qs_locs = (const float*)d_in[3];
    const float* ks_locs = (const float*)d_in[4];
    const float* Wq      = (const float*)d_in[5];
    const float* bq      = (const float*)d_in[6];
    const float* Wk      = (const float*)d_in[7];
    const float* bk      = (const float*)d_in[8];
    const float* Wv      = (const float*)d_in[9];
    const float* bv      = (const float*)d_in[10];
    const float* Wo      = (const float*)d_in[11];
    const float* bo      = (const float*)d_in[12];
    const float* a       = (const float*)d_in[13];
    const float* b       = (const float*)d_in[14];
    const float* c       = (const float*)d_in[15];
    const int*   vlens   = (const int*)d_in[16];

    float *p_q, *p_v, *p_ctx;
    unsigned *p_wb, *p_ws;
    cudaGetSymbolAddress((void**)&p_q,   g_q);
    cudaGetSymbolAddress((void**)&p_v,   g_v);
    cudaGetSymbolAddress((void**)&p_ctx, g_ctx);
    cudaGetSymbolAddress((void**)&p_wb,  g_wb);
    cudaGetSymbolAddress((void**)&p_ws,  g_ws);

    cudaFuncSetAttribute(attn_kernel, cudaFuncAttributeMaxDynamicSharedMemorySize, ATTN_SMEM);
    cudaFuncSetAttribute(gemm_f16_kernel, cudaFuncAttributeMaxDynamicSharedMemorySize, GEMM_SMEM);

    const int WMAT = DMODEL * (DMODEL / 2);
    const float L2E = 1.4426950408889634f;

    PackWBatch pw;
    pw.in[0] = Wq; pw.in[1] = Wk; pw.in[2] = Wv; pw.in[3] = Wo;
    pack_w_kernel<<<dim3(16, 16, 4), dim3(32, 8)>>>(pw);

    GemmBatch gqkv;
    gqkv.A[0] = qs; gqkv.A[1] = ks; gqkv.A[2] = vs;
    gqkv.Wb[0] = p_wb;            gqkv.Ws[0] = p_ws;
    gqkv.Wb[1] = p_wb + WMAT;     gqkv.Ws[1] = p_ws + WMAT;
    gqkv.Wb[2] = p_wb + 2 * WMAT; gqkv.Ws[2] = p_ws + 2 * WMAT;
    gqkv.bias[0] = bq; gqkv.bias[1] = bk; gqkv.bias[2] = bv;
    gqkv.C[0] = p_q; gqkv.C[1] = nullptr; gqkv.C[2] = p_v;
    gqkv.scale[0] = L2E / 8.0f; gqkv.scale[1] = 1.0f; gqkv.scale[2] = 1.0f;
    gqkv.omode[0] = 0; gqkv.omode[1] = 1; gqkv.omode[2] = 0;
    gemm_f16_kernel<<<dim3(DMODEL / 64, (BB * QQ) / 128, 3), 256, GEMM_SMEM>>>(gqkv);

    pack_v_kernel<<<dim3(KSEQ / 64, BB * NH), 256>>>();

    attn_kernel<<<dim3(QQ / 128, BB * NH), 256, ATTN_SMEM>>>(
        qs_locs, ks_locs, a, b, c, vlens);

    GemmBatch go;
    go.A[0] = p_ctx; go.A[1] = p_ctx; go.A[2] = p_ctx;
    go.Wb[0] = p_wb + 3 * WMAT; go.Ws[0] = p_ws + 3 * WMAT;
    go.Wb[1] = go.Wb[0]; go.Ws[1] = go.Ws[0];
    go.Wb[2] = go.Wb[0]; go.Ws[2] = go.Ws[0];
    go.bias[0] = bo; go.bias[1] = bo; go.bias[2] = bo;
    go.C[0] = (float*)d_out; go.C[1] = (float*)d_out; go.C[2] = (float*)d_out;
    go.scale[0] = 1.0f; go.scale[1] = 1.0f; go.scale[2] = 1.0f;
    go.omode[0] = 0; go.omode[1] = 0; go.omode[2] = 0;
    gemm_f16_kernel<<<dim3(DMODEL / 64, (BB * QQ) / 128, 1), 256, GEMM_SMEM>>>(go);
}

// round 13
// speedup vs baseline: 1.1081x; 1.1081x over previous
#include <cuda_runtime.h>
#include <cuda_fp16.h>
#include <math.h>

#define BB 2
#define QQ 2048
#define KSEQ 2048
#define DMODEL 512
#define NH 8
#define NF 5
#define DH 64

// Scratch (no cudaMalloc allowed)
__device__ float g_q[BB * QQ * DMODEL];
__device__ float g_v[BB * KSEQ * DMODEL];
__device__ float g_ctx[BB * QQ * DMODEL];
__device__ unsigned g_kh[BB * NH * KSEQ * 32];          // K fp16 packed dh-pairs
__device__ unsigned g_vh[BB * NH * DH * (KSEQ / 2)];    // V fp16 packed key-pairs
__device__ unsigned g_wb[4 * DMODEL * (DMODEL / 2)];    // W big fp16, [n][kpair]
__device__ unsigned g_ws[4 * DMODEL * (DMODEL / 2)];    // W small fp16

__device__ __forceinline__ float ex2f(float x) { float r; asm("ex2.approx.f32 %0, %1;" : "=f"(r) : "f"(x)); return r; }
__device__ __forceinline__ float sqrt_ap(float x) { float r; asm("sqrt.approx.f32 %0, %1;" : "=f"(r) : "f"(x)); return r; }
__device__ __forceinline__ unsigned packh2(float x, float y) {
    __half2 h = __floats2half2_rn(x, y);
    return *reinterpret_cast<unsigned*>(&h);
}
__device__ __forceinline__ unsigned smaddr(const void* p) {
    unsigned r;
    asm("{ .reg .u64 t; cvta.to.shared.u64 t, %1; cvt.u32.u64 %0, t; }" : "=r"(r) : "l"(p));
    return r;
}
__device__ __forceinline__ void ldsm4(unsigned& r0, unsigned& r1, unsigned& r2, unsigned& r3, unsigned a) {
    asm volatile("ldmatrix.sync.aligned.m8n8.x4.shared.b16 {%0,%1,%2,%3}, [%4];"
                 : "=r"(r0), "=r"(r1), "=r"(r2), "=r"(r3) : "r"(a));
}

#define CP16(dst, src) asm volatile("cp.async.cg.shared.global [%0], [%1], 16;" :: "r"(dst), "l"(src))
#define CP_COMMIT()    asm volatile("cp.async.commit_group;")
#define CP_WAIT0()     asm volatile("cp.async.wait_group 0;" ::: "memory")
#define CP_WAIT1()     asm volatile("cp.async.wait_group 1;" ::: "memory")

#define MMA_F16(C, A0, A1, A2, A3, B0, B1)                                  \
    asm volatile("mma.sync.aligned.m16n8k16.row.col.f32.f16.f16.f32 "       \
        "{%0,%1,%2,%3}, {%4,%5,%6,%7}, {%8,%9}, {%0,%1,%2,%3};"             \
        : "+f"((C)[0]), "+f"((C)[1]), "+f"((C)[2]), "+f"((C)[3])            \
        : "r"(A0), "r"(A1), "r"(A2), "r"(A3), "r"(B0), "r"(B1))

// ---------------------------------------------------------------------------
// Pack W: split into fp16 big + fp16 small, transposed to [n][kpair] packed.
// ---------------------------------------------------------------------------
struct PackWBatch { const float* in[4]; };

__global__ void pack_w_kernel(PackWBatch args)
{
    __shared__ float t[32][33];
    const float* in = args.in[blockIdx.z];
    unsigned zoff = blockIdx.z * DMODEL * (DMODEL / 2);
    int k0 = blockIdx.y * 32, n0 = blockIdx.x * 32;
    int tx = threadIdx.x, ty = threadIdx.y;
    #pragma unroll
    for (int j = 0; j < 4; j++)
        t[ty + j * 8][tx] = in[(size_t)(k0 + ty + j * 8) * DMODEL + n0 + tx];
    __syncthreads();
    int idx = ty * 32 + tx;
    int kp = idx & 15, nl = idx >> 4;
    #pragma unroll
    for (int j2 = 0; j2 < 2; j2++) {
        int n = nl + j2 * 16;
        float w0 = t[2 * kp][n], w1 = t[2 * kp + 1][n];
        __half2 hb = __floats2half2_rn(w0, w1);
        float s0 = w0 - __low2float(hb);
        float s1 = w1 - __high2float(hb);
        unsigned ub = *reinterpret_cast<unsigned*>(&hb);
        size_t o = zoff + (size_t)(n0 + n) * 256 + (k0 >> 1) + kp;
        g_wb[o] = ub;
        g_ws[o] = packh2(s0, s1);
    }
}

// ---------------------------------------------------------------------------
// Pack V: fp32 [b][key][DM] -> fp16 key-pair packed [b][h][dh][kp]
// ---------------------------------------------------------------------------
__global__ __launch_bounds__(256) void pack_v_kernel()
{
    __shared__ unsigned sv[64 * 64];
    int bh = blockIdx.y;
    int b = bh >> 3, h = bh & 7;
    int k0 = blockIdx.x * 64;
    int tid = threadIdx.x;
    int dh = tid & 63, kq = tid >> 6;
    const float* vb = g_v + (size_t)(b * KSEQ + k0) * DMODEL + h * DH + dh;
    #pragma unroll
    for (int j = 0; j < 8; j++) {
        int kp = kq * 8 + j;
        float r0 = vb[(size_t)(2 * kp) * DMODEL];
        float r1 = vb[(size_t)(2 * kp + 1) * DMODEL];
        sv[kp * 64 + dh] = packh2(r0, r1);
    }
    __syncthreads();
    int row = tid >> 2, cs = (tid & 3) * 8;
    unsigned* ob = g_vh + ((size_t)(b * NH + h) * DH + row) * (KSEQ / 2) + (k0 >> 1) + cs;
    #pragma unroll
    for (int q = 0; q < 2; q++) {
        uint4 v;
        v.x = sv[(cs + q * 4 + 0) * 64 + row];
        v.y = sv[(cs + q * 4 + 1) * 64 + row];
        v.z = sv[(cs + q * 4 + 2) * 64 + row];
        v.w = sv[(cs + q * 4 + 3) * 64 + row];
        *(uint4*)(ob + q * 4) = v;
    }
}

// ---------------------------------------------------------------------------
// fp16 2-mma GEMM (R11 version): CTA 128x128, BK=32, 8 warps (32x64 each).
// Pipeline: wait -> sync -> issue-next-W -> mma -> store-next-A.
// ---------------------------------------------------------------------------
struct GemmBatch {
    const float* A[3]; const unsigned* Wb[3]; const unsigned* Ws[3];
    const float* bias[3]; float* C[3]; float scale[3]; int omode[3];
};

#define GS 20
#define GBUF (128 * GS)
#define GEMM_SMEM (2 * 3 * GBUF * 4)

__global__ __launch_bounds__(256) void gemm_f16_kernel(GemmBatch args)
{
    extern __shared__ unsigned su[];

    int z = blockIdx.z;
    const float* A = args.A[z];
    const float* bias = args.bias[z];
    float* C = args.C[z];
    float scale = args.scale[z];
    int omode = args.omode[z];

    int tid = threadIdx.x, w = tid >> 5, lane = tid & 31;
    int g = lane >> 2, tig = lane & 3;
    int row0 = blockIdx.y * 128, col0 = blockIdx.x * 128;
    int wm = (w & 3) * 32, wn = (w >> 2) * 64;

    float acc[2][8][4];
    #pragma unroll
    for (int mf = 0; mf < 2; mf++)
        #pragma unroll
        for (int nf = 0; nf < 8; nf++)
            acc[mf][nf][0] = acc[mf][nf][1] = acc[mf][nf][2] = acc[mf][nf][3] = 0.f;

    int r = tid >> 1, c0 = (tid & 1) << 3;
    const float* Ap = A + (size_t)(row0 + r) * DMODEL + (c0 << 1);
    const unsigned* Wbp = args.Wb[z] + (size_t)(col0 + r) * 256 + c0;
    const unsigned* Wsp = args.Ws[z] + (size_t)(col0 + r) * 256 + c0;
    unsigned sb = smaddr(su);

    float4 av[4];
    #pragma unroll
    for (int j = 0; j < 4; j++) av[j] = *(const float4*)(Ap + j * 4);

    #define STS_A(st)                                                        \
    do {                                                                     \
        unsigned* Ah_ = su + (st) * 3 * GBUF;                                \
        uint4 p0, p1;                                                        \
        p0.x = packh2(av[0].x, av[0].y); p0.y = packh2(av[0].z, av[0].w);    \
        p0.z = packh2(av[1].x, av[1].y); p0.w = packh2(av[1].z, av[1].w);    \
        p1.x = packh2(av[2].x, av[2].y); p1.y = packh2(av[2].z, av[2].w);    \
        p1.z = packh2(av[3].x, av[3].y); p1.w = packh2(av[3].z, av[3].w);    \
        *(uint4*)&Ah_[r * GS + c0] = p0;                                     \
        *(uint4*)&Ah_[r * GS + c0 + 4] = p1;                                 \
    } while (0)

    #define ISSUE_W(it, st)                                                  \
    do {                                                                     \
        unsigned wbd = sb + ((st) * 3 * GBUF + GBUF + r * GS + c0) * 4;      \
        unsigned wsd = wbd + GBUF * 4;                                       \
        CP16(wbd, Wbp + (it) * 16);                                          \
        CP16(wbd + 16, Wbp + (it) * 16 + 4);                                 \
        CP16(wsd, Wsp + (it) * 16);                                          \
        CP16(wsd + 16, Wsp + (it) * 16 + 4);                                 \
        CP_COMMIT();                                                         \
    } while (0)

    STS_A(0);
    ISSUE_W(0, 0);

    const int NT = DMODEL / 32;   // 16
    for (int it = 0; it < NT; it++) {
        int cur = it & 1;
        bool nx = (it + 1) < NT;
        if (nx) {
            #pragma unroll
            for (int j = 0; j < 4; j++)
                av[j] = *(const float4*)(Ap + (it + 1) * 32 + j * 4);
        }
        CP_WAIT0();
        __syncthreads();
        if (nx) ISSUE_W(it + 1, cur ^ 1);   // after sync: WAR-safe

        unsigned* Ah = su + cur * 3 * GBUF;
        unsigned* Wbm = Ah + GBUF;
        unsigned* Wsm = Ah + 2 * GBUF;

        #pragma unroll
        for (int s = 0; s < 2; s++) {
            unsigned af[2][4];
            #pragma unroll
            for (int mf = 0; mf < 2; mf++) {
                int rb = (wm + mf * 16 + g) * GS;
                int cb = s * 8 + tig;
                af[mf][0] = Ah[rb + cb];
                af[mf][1] = Ah[rb + 8 * GS + cb];
                af[mf][2] = Ah[rb + cb + 4];
                af[mf][3] = Ah[rb + 8 * GS + cb + 4];
            }
            #pragma unroll
            for (int nf = 0; nf < 8; nf++) {
                int br = (wn + nf * 8 + g) * GS + s * 8 + tig;
                unsigned bb0 = Wbm[br], bb1 = Wbm[br + 4];
                unsigned bs0 = Wsm[br], bs1 = Wsm[br + 4];
                #pragma unroll
                for (int mf = 0; mf < 2; mf++) {
                    MMA_F16(acc[mf][nf], af[mf][0], af[mf][1], af[mf][2], af[mf][3], bs0, bs1);
                    MMA_F16(acc[mf][nf], af[mf][0], af[mf][1], af[mf][2], af[mf][3], bb0, bb1);
                }
            }
        }
        if (nx) STS_A(cur ^ 1);
    }
    #undef STS_A
    #undef ISSUE_W

    if (omode == 0) {
        #pragma unroll
        for (int mf = 0; mf < 2; mf++) {
            int rr = row0 + wm + mf * 16 + g;
            #pragma unroll
            for (int nf = 0; nf < 8; nf++) {
                int n = col0 + wn + nf * 8 + 2 * tig;
                float2 bv = *(const float2*)&bias[n];
                *(float2*)&C[(size_t)rr * DMODEL + n] =
                    make_float2((acc[mf][nf][0] + bv.x) * scale, (acc[mf][nf][1] + bv.y) * scale);
                *(float2*)&C[(size_t)(rr + 8) * DMODEL + n] =
                    make_float2((acc[mf][nf][2] + bv.x) * scale, (acc[mf][nf][3] + bv.y) * scale);
            }
        }
    } else {
        #pragma unroll
        for (int mf = 0; mf < 2; mf++) {
            int rr = row0 + wm + mf * 16 + g;
            #pragma unroll
            for (int nf = 0; nf < 8; nf++) {
                int n = col0 + wn + nf * 8 + 2 * tig;
                float2 bv = *(const float2*)&bias[n];
                int h = n >> 6, dhp = (n & 63) >> 1;
                int b0 = rr >> 11, key0 = rr & 2047;
                g_kh[((size_t)(b0 * NH + h) * KSEQ + key0) * 32 + dhp] =
                    packh2(acc[mf][nf][0] + bv.x, acc[mf][nf][1] + bv.y);
                int rr1 = rr + 8;
                int b1 = rr1 >> 11, key1 = rr1 & 2047;
                g_kh[((size_t)(b1 * NH + h) * KSEQ + key1) * 32 + dhp] =
                    packh2(acc[mf][nf][2] + bv.x, acc[mf][nf][3] + bv.y);
            }
        }
    }
}

// ---------------------------------------------------------------------------
// fp16 flash attention (R12 version): bias folded into accumulator init,
// Q pre-scaled by log2e/8, LUT pre-folded (x*L2E + MB), ldmatrix.x4 frags,
// 3-stage cp.async ring, epilogue = min+ex2 only.
// ---------------------------------------------------------------------------
#define TBL 2048
#define SSZ 4736   // u32/stage: K 64*36 + V 64*36 + Kloc 128
#define NSTG 3
#define ATTN_SMEM ((NSTG * SSZ + 2 * TBL) * 4)

__global__ __launch_bounds__(256, 2) void attn_kernel(
    const float* __restrict__ qlocs_g, const float* __restrict__ klocs_g,
    const float* __restrict__ a_g, const float* __restrict__ b_g,
    const float* __restrict__ c_g, const int* __restrict__ valid_lens)
{
    extern __shared__ unsigned smu[];
    float* Tbl = (float*)(smu + NSTG * SSZ);

    const float L2E = 1.4426950408889634f;
    const float MB = -13.0831206542234f;        // -(16*log2e - 10)
    const float IDXS = 2047.0f / 14.2f;
    const float INVS = 14.2f / 2047.0f;

    int bh = blockIdx.y;
    int b = bh >> 3, h = bh & 7;
    int q0 = blockIdx.x * 128;
    int tid = threadIdx.x, w = tid >> 5, lane = tid & 31;
    int g = lane >> 2, tig = lane & 3;
    int vlen = valid_lens[b];

    // ---- RBF bias LUT: entry = (bias(x)*L2E + MB, dbias*L2E) ----
    {
        float af[NF], al[NF], be[NF], ga[NF];
        #pragma unroll
        for (int f = 0; f < NF; f++) {
            float aa = a_g[h * NF + f];
            float bb = fabsf(b_g[h * NF + f]);
            float cc = c_g[h * NF + f];
            af[f] = aa;
            al[f] = -bb * L2E;
            be[f] = 2.0f * bb * cc * L2E;
            ga[f] = -bb * cc * cc * L2E;
        }
        for (int i = tid; i < TBL; i += 256) {
            float x0 = i * INVS, x1 = (i + 1) * INVS;
            float v0 = 0.f, v1 = 0.f;
            #pragma unroll
            for (int f = 0; f < NF; f++) {
                v0 = fmaf(af[f], ex2f(fmaf(fmaf(al[f], x0, be[f]), x0, ga[f])), v0);
                v1 = fmaf(af[f], ex2f(fmaf(fmaf(al[f], x1, be[f]), x1, ga[f])), v1);
            }
            *(float2*)&Tbl[2 * i] = make_float2(fmaf(v0, L2E, MB), (v1 - v0) * L2E);
        }
    }

    // ---- query rows, locations, hoisted Q fragments (Q already *L2E/8) ----
    int qr0 = q0 + w * 16 + g, qr1 = qr0 + 8;
    float2 ql0 = *(const float2*)(qlocs_g + ((size_t)b * QQ + qr0) * 2);
    float2 ql1 = *(const float2*)(qlocs_g + ((size_t)b * QQ + qr1) * 2);

    unsigned qf[4][4];
    {
        const float* qp0 = g_q + ((size_t)(b * QQ + qr0)) * DMODEL + h * DH;
        const float* qp1 = g_q + ((size_t)(b * QQ + qr1)) * DMODEL + h * DH;
        #pragma unroll
        for (int kt = 0; kt < 4; kt++) {
            int base = kt * 16 + 2 * tig;
            float2 x0 = *(const float2*)(qp0 + base);
            float2 x1 = *(const float2*)(qp1 + base);
            float2 x2 = *(const float2*)(qp0 + base + 8);
            float2 x3 = *(const float2*)(qp1 + base + 8);
            qf[kt][0] = packh2(x0.x, x0.y);
            qf[kt][1] = packh2(x1.x, x1.y);
            qf[kt][2] = packh2(x2.x, x2.y);
            qf[kt][3] = packh2(x3.x, x3.y);
        }
    }

    float o[8][4];
    #pragma unroll
    for (int nt = 0; nt < 8; nt++)
        o[nt][0] = o[nt][1] = o[nt][2] = o[nt][3] = 0.f;
    float rs0 = 0.f, rs1 = 0.f;

    unsigned sb = smaddr(smu);
    const unsigned* khb = g_kh + (size_t)(b * NH + h) * KSEQ * 32;
    const unsigned* vhb = g_vh + (size_t)(b * NH + h) * DH * (KSEQ / 2);
    const float* klocs_b = klocs_g + (size_t)b * KSEQ * 2;

    unsigned kofs = ((unsigned)((lane >> 4) * 8 + (lane & 7))) * 144u
                  + ((unsigned)((lane >> 3) & 1)) * 16u;

    int ntiles = (vlen + 63) >> 6;

    #define ISSUE_TILE(t, st)                                                \
    do {                                                                     \
        int k0_ = (t) << 6;                                                  \
        unsigned kd = sb + (st) * SSZ * 4;                                   \
        unsigned vd = kd + 2304 * 4;                                         \
        _Pragma("unroll")                                                    \
        for (int i = 0; i < 2; i++) {                                        \
            int idx = tid + i * 256;                                         \
            int row = idx >> 3, ch = (idx & 7) << 2;                         \
            CP16(kd + (row * 36 + ch) * 4, khb + (size_t)(k0_ + row) * 32 + ch); \
            CP16(vd + (row * 36 + ch) * 4, vhb + (size_t)row * (KSEQ / 2) + (k0_ >> 1) + ch); \
        }                                                                    \
        if (tid < 32)                                                        \
            CP16(kd + (4608 + tid * 4) * 4, klocs_b + k0_ * 2 + tid * 4);    \
        CP_COMMIT();                                                         \
    } while (0)

    ISSUE_TILE(0, 0);
    if (ntiles > 1) ISSUE_TILE(1, 1);
    __syncthreads();   // Tbl ready

    int st = 0, ist = 2;
    for (int t = 0; t < ntiles; t++) {
        int k0 = t << 6;
        if (t + 1 < ntiles) CP_WAIT1(); else CP_WAIT0();
        __syncthreads();
        if (t + 2 < ntiles) {
            ISSUE_TILE(t + 2, ist);
            ist = (ist == NSTG - 1) ? 0 : ist + 1;
        }

        unsigned kSm = sb + st * SSZ * 4;
        unsigned vSm = kSm + 2304 * 4;
        const float* Kloc = (const float*)(smu + st * SSZ + 4608);

        // ---- bias -> Sv (accumulator init), BEFORE the mma ----
        float Sv[8][4];
        #pragma unroll
        for (int nt = 0; nt < 8; nt++) {
            int kc0 = nt * 8 + 2 * tig;
            float2 kl0 = *(const float2*)&Kloc[kc0 * 2];
            float2 kl1 = *(const float2*)&Kloc[kc0 * 2 + 2];

            float dx, dy;
            dx = ql0.x - kl0.x; dy = ql0.y - kl0.y; float d0 = sqrt_ap(dx * dx + dy * dy);
            dx = ql0.x - kl1.x; dy = ql0.y - kl1.y; float d1 = sqrt_ap(dx * dx + dy * dy);
            dx = ql1.x - kl0.x; dy = ql1.y - kl0.y; float d2 = sqrt_ap(dx * dx + dy * dy);
            dx = ql1.x - kl1.x; dy = ql1.y - kl1.y; float d3 = sqrt_ap(dx * dx + dy * dy);

            float if0 = d0 * IDXS; int i0 = (int)if0; float fr0 = if0 - (float)i0;
            float if1 = d1 * IDXS; int i1 = (int)if1; float fr1 = if1 - (float)i1;
            float if2 = d2 * IDXS; int i2 = (int)if2; float fr2 = if2 - (float)i2;
            float if3 = d3 * IDXS; int i3 = (int)if3; float fr3 = if3 - (float)i3;
            float2 t0 = *(const float2*)&Tbl[i0 * 2];
            float2 t1 = *(const float2*)&Tbl[i1 * 2];
            float2 t2 = *(const float2*)&Tbl[i2 * 2];
            float2 t3 = *(const float2*)&Tbl[i3 * 2];

            Sv[nt][0] = fmaf(fr0, t0.y, t0.x);
            Sv[nt][1] = fmaf(fr1, t1.y, t1.x);
            Sv[nt][2] = fmaf(fr2, t2.y, t2.x);
            Sv[nt][3] = fmaf(fr3, t3.y, t3.x);
        }

        // ---- Sv += Q K^T (log2e units) via ldmatrix + mma ----
        #pragma unroll
        for (int kt = 0; kt < 4; kt++) {
            #pragma unroll
            for (int i = 0; i < 4; i++) {
                unsigned m0, m1, m2, m3;
                ldsm4(m0, m1, m2, m3, kSm + i * 2304 + kt * 32 + kofs);
                MMA_F16(Sv[2 * i],     qf[kt][0], qf[kt][1], qf[kt][2], qf[kt][3], m0, m1);
                MMA_F16(Sv[2 * i + 1], qf[kt][0], qf[kt][1], qf[kt][2], qf[kt][3], m2, m3);
            }
        }

        // ---- p = ex2(min(Sv, 15)); mask; accumulate row sums ----
        bool full = (k0 + 64) <= vlen;
        #pragma unroll
        for (int nt = 0; nt < 8; nt++) {
            float p0 = ex2f(fminf(Sv[nt][0], 15.0f));
            float p1 = ex2f(fminf(Sv[nt][1], 15.0f));
            float p2 = ex2f(fminf(Sv[nt][2], 15.0f));
            float p3 = ex2f(fminf(Sv[nt][3], 15.0f));
            if (!full) {
                int kc0 = nt * 8 + 2 * tig;
                if (k0 + kc0     >= vlen) { p0 = 0.f; p2 = 0.f; }
                if (k0 + kc0 + 1 >= vlen) { p1 = 0.f; p3 = 0.f; }
            }
            rs0 += p0 + p1;
            rs1 += p2 + p3;
            Sv[nt][0] = p0; Sv[nt][1] = p1; Sv[nt][2] = p2; Sv[nt][3] = p3;
        }

        // ---- O += P V (C-frag pairs pack directly as A-frags) ----
        #pragma unroll
        for (int j = 0; j < 4; j++) {
            unsigned a0 = packh2(Sv[2 * j][0], Sv[2 * j][1]);
            unsigned a1 = packh2(Sv[2 * j][2], Sv[2 * j][3]);
            unsigned a2 = packh2(Sv[2 * j + 1][0], Sv[2 * j + 1][1]);
            unsigned a3 = packh2(Sv[2 * j + 1][2], Sv[2 * j + 1][3]);
            #pragma unroll
            for (int i = 0; i < 4; i++) {
                unsigned m0, m1, m2, m3;
                ldsm4(m0, m1, m2, m3, vSm + i * 2304 + j * 32 + kofs);
                MMA_F16(o[2 * i],     a0, a1, a2, a3, m0, m1);
                MMA_F16(o[2 * i + 1], a0, a1, a2, a3, m2, m3);
            }
        }
        st = (st == NSTG - 1) ? 0 : st + 1;
    }
    #undef ISSUE_TILE

    // ---- normalize + write ----
    rs0 += __shfl_xor_sync(0xffffffffu, rs0, 1);
    rs0 += __shfl_xor_sync(0xffffffffu, rs0, 2);
    rs1 += __shfl_xor_sync(0xffffffffu, rs1, 1);
    rs1 += __shfl_xor_sync(0xffffffffu, rs1, 2);
    float inv0 = 1.0f / rs0, inv1 = 1.0f / rs1;

    float* ob0 = g_ctx + ((size_t)b * QQ + qr0) * DMODEL + h * DH;
    float* ob1 = g_ctx + ((size_t)b * QQ + qr1) * DMODEL + h * DH;
    #pragma unroll
    for (int nt = 0; nt < 8; nt++) {
        *(float2*)(ob0 + nt * 8 + 2 * tig) = make_float2(o[nt][0] * inv0, o[nt][1] * inv0);
        *(float2*)(ob1 + nt * 8 + 2 * tig) = make_float2(o[nt][2] * inv1, o[nt][3] * inv1);
    }
}

// ---------------------------------------------------------------------------
extern "C" void kernel_launch(void* const* d_in, const int* in_sizes, int n_in,
                              void* d_out, int out_size)
{
    const float* qs      = (const float*)d_in[0];
    const float* ks      = (const float*)d_in[1];
    const float* vs      = (const float*)d_in[2];
    const float* qs_locs = (const float*)d_in[3];
    const float* ks_locs = (const float*)d_in[4];
    const float* Wq      = (const float*)d_in[5];
    const float* bq      = (const float*)d_in[6];
    const float* Wk      = (const float*)d_in[7];
    const float* bk      = (const float*)d_in[8];
    const float* Wv      = (const float*)d_in[9];
    const float* bv      = (const float*)d_in[10];
    const float* Wo      = (const float*)d_in[11];
    const float* bo      = (const float*)d_in[12];
    const float* a       = (const float*)d_in[13];
    const float* b       = (const float*)d_in[14];
    const float* c       = (const float*)d_in[15];
    const int*   vlens   = (const int*)d_in[16];

    float *p_q, *p_v, *p_ctx;
    unsigned *p_wb, *p_ws;
    cudaGetSymbolAddress((void**)&p_q,   g_q);
    cudaGetSymbolAddress((void**)&p_v,   g_v);
    cudaGetSymbolAddress((void**)&p_ctx, g_ctx);
    cudaGetSymbolAddress((void**)&p_wb,  g_wb);
    cudaGetSymbolAddress((void**)&p_ws,  g_ws);

    cudaFuncSetAttribute(attn_kernel, cudaFuncAttributeMaxDynamicSharedMemorySize, ATTN_SMEM);
    cudaFuncSetAttribute(gemm_f16_kernel, cudaFuncAttributeMaxDynamicSharedMemorySize, GEMM_SMEM);

    const int WMAT = DMODEL * (DMODEL / 2);
    const float L2E = 1.4426950408889634f;

    PackWBatch pw;
    pw.in[0] = Wq; pw.in[1] = Wk; pw.in[2] = Wv; pw.in[3] = Wo;
    pack_w_kernel<<<dim3(16, 16, 4), dim3(32, 8)>>>(pw);

    GemmBatch gqkv;
    gqkv.A[0] = qs; gqkv.A[1] = ks; gqkv.A[2] = vs;
    gqkv.Wb[0] = p_wb;            gqkv.Ws[0] = p_ws;
    gqkv.Wb[1] = p_wb + WMAT;     gqkv.Ws[1] = p_ws + WMAT;
    gqkv.Wb[2] = p_wb + 2 * WMAT; gqkv.Ws[2] = p_ws + 2 * WMAT;
    gqkv.bias[0] = bq; gqkv.bias[1] = bk; gqkv.bias[2] = bv;
    gqkv.C[0] = p_q; gqkv.C[1] = nullptr; gqkv.C[2] = p_v;
    gqkv.scale[0] = L2E / 8.0f; gqkv.scale[1] = 1.0f; gqkv.scale[2] = 1.0f;
    gqkv.omode[0] = 0; gqkv.omode[1] = 1; gqkv.omode[2] = 0;
    gemm_f16_kernel<<<dim3(DMODEL / 128, (BB * QQ) / 128, 3), 256, GEMM_SMEM>>>(gqkv);

    pack_v_kernel<<<dim3(KSEQ / 64, BB * NH), 256>>>();

    attn_kernel<<<dim3(QQ / 128, BB * NH), 256, ATTN_SMEM>>>(
        qs_locs, ks_locs, a, b, c, vlens);

    GemmBatch go;
    go.A[0] = p_ctx; go.A[1] = p_ctx; go.A[2] = p_ctx;
    go.Wb[0] = p_wb + 3 * WMAT; go.Ws[0] = p_ws + 3 * WMAT;
    go.Wb[1] = go.Wb[0]; go.Ws[1] = go.Ws[0];
    go.Wb[2] = go.Wb[0]; go.Ws[2] = go.Ws[0];
    go.bias[0] = bo; go.bias[1] = bo; go.bias[2] = bo;
    go.C[0] = (float*)d_out; go.C[1] = (float*)d_out; go.C[2] = (float*)d_out;
    go.scale[0] = 1.0f; go.scale[1] = 1.0f; go.scale[2] = 1.0f;
    go.omode[0] = 0; go.omode[1] = 0; go.omode[2] = 0;
    gemm_f16_kernel<<<dim3(DMODEL / 128, (BB * QQ) / 128, 1), 256, GEMM_SMEM>>>(go);
}